// round 12
// baseline (speedup 1.0000x reference)
#include <cuda_runtime.h>
#include <cstdint>

#define B 32
#define F 1024
#define S 2048
#define KK 16
#define NSPLIT 8
#define RPS (S / NSPLIT)          // 256 rows per split
#define BLKS_PER_BATCH 32         // (S/(128*4)) * NSPLIT = 4*8

// Scratch (allocation-free rule: __device__ globals)
__device__ float g_partial[B * NSPLIT * S];   // 2 MB partial column sums
__device__ int   g_idx[B * KK];               // top-k indices per batch
__device__ unsigned int g_count[B];           // arrival counters (self-reset)

static __device__ __forceinline__ unsigned long long u64max(
    unsigned long long a, unsigned long long b) { return a > b ? a : b; }

// ---------------------------------------------------------------------------
// Kernel 1 (fused): partial column sums of w[B,S,S] + last-block-per-batch
// fold & top-16 epilogue.
// Main body = EXACT measured-best colsum (float4 __ldg, unroll 8, 128 thr).
// Epilogue (32nd arriving block of the batch only):
//   - fold 8 partials (L2-hot), build packed sort keys in smem,
//   - quad-shuffle group maxes (32 groups of 64 cols),
//   - warp-0 tournament: 16 rounds of {5-shfl argmax, mask winner,
//     64-entry group rescan, 5-shfl reduce} — no block barriers per round.
// Key = (monotone float bits << 32) | (S-1-col): max key = largest value,
// ties broken toward the LOWEST column index (matches lax.top_k).
// ---------------------------------------------------------------------------
__global__ void colsum_topk_kernel(const float* __restrict__ w) {
    __shared__ unsigned long long skey[S];          // 16 KB
    __shared__ unsigned long long groupmax[32];
    __shared__ int s_last;

    const int c4    = blockIdx.x * blockDim.x + threadIdx.x;  // float4 col group
    const int split = blockIdx.y;
    const int b     = blockIdx.z;
    const int t     = threadIdx.x;                  // 0..127
    const int lane  = t & 31;

    // ---- colsum main body (DO NOT TOUCH: 83.7% DRAM measured) ----
    const float4* wp = reinterpret_cast<const float4*>(w + (size_t)b * S * S);
    const float4* p  = wp + (size_t)(split * RPS) * (S / 4) + c4;

    float4 acc = make_float4(0.f, 0.f, 0.f, 0.f);
#pragma unroll 8
    for (int r = 0; r < RPS; ++r) {
        float4 v = __ldg(p);
        acc.x += v.x; acc.y += v.y; acc.z += v.z; acc.w += v.w;
        p += S / 4;
    }

    float4* outp = reinterpret_cast<float4*>(g_partial)
                 + (size_t)(b * NSPLIT + split) * (S / 4) + c4;
    *outp = acc;

    // ---- arrival count (threadfence-reduction pattern) ----
    __threadfence();
    __syncthreads();
    if (t == 0) {
        unsigned int old = atomicInc(&g_count[b], BLKS_PER_BATCH - 1);
        s_last = (old == BLKS_PER_BATCH - 1);       // wraps to 0: replay-safe
    }
    __syncthreads();
    if (!s_last) return;

    // ---- epilogue: fold 8 partials for this batch (thread t: cols 16t..16t+15)
    unsigned long long kmax = 0ull;
#pragma unroll
    for (int j = 0; j < 4; ++j) {
        const int g4 = 4 * t + j;                   // float4 col group
        float4 s = make_float4(0.f, 0.f, 0.f, 0.f);
#pragma unroll
        for (int pp = 0; pp < NSPLIT; ++pp) {
            float4 v = *(reinterpret_cast<const float4*>(g_partial)
                         + (size_t)(b * NSPLIT + pp) * (S / 4) + g4);
            s.x += v.x; s.y += v.y; s.z += v.z; s.w += v.w;
        }
        const float sv[4] = {s.x, s.y, s.z, s.w};
#pragma unroll
        for (int e = 0; e < 4; ++e) {
            const int c = 4 * g4 + e;
            unsigned int bits = __float_as_uint(sv[e]);
            bits = (bits & 0x80000000u) ? ~bits : (bits | 0x80000000u);
            unsigned long long key = ((unsigned long long)bits << 32)
                                   | (unsigned int)(S - 1 - c);
            skey[c] = key;
            kmax = u64max(kmax, key);
        }
    }
    // quad reduce: threads 4q..4q+3 cover 64-col group q
    kmax = u64max(kmax, __shfl_down_sync(0xffffffffu, kmax, 2, 4));
    kmax = u64max(kmax, __shfl_down_sync(0xffffffffu, kmax, 1, 4));
    if ((t & 3) == 0) groupmax[t >> 2] = kmax;
    __syncthreads();

    // ---- warp-0 tournament ----
    if (t < 32) {
        unsigned long long gm = groupmax[lane];     // lane l owns group l

        for (int k = 0; k < KK; ++k) {
            unsigned long long m = gm;
#pragma unroll
            for (int off = 16; off > 0; off >>= 1)
                m = u64max(m, __shfl_down_sync(0xffffffffu, m, off));
            m = __shfl_sync(0xffffffffu, m, 0);

            const int col = S - 1 - (int)(m & 0xFFFFFFFFu);
            if (lane == 0) {
                g_idx[b * KK + k] = col;
                skey[col] = 0ull;                   // mask the winner
            }
            __syncwarp();

            const int g = col >> 6;                 // rescan winner's group
            unsigned long long a0 = skey[(g << 6) + lane];
            unsigned long long a1 = skey[(g << 6) + 32 + lane];
            unsigned long long mm = u64max(a0, a1);
#pragma unroll
            for (int off = 16; off > 0; off >>= 1)
                mm = u64max(mm, __shfl_down_sync(0xffffffffu, mm, off));
            mm = __shfl_sync(0xffffffffu, mm, 0);
            if (lane == g) gm = mm;
        }
    }
}

// ---------------------------------------------------------------------------
// Kernel 2: gather out[b,f,k] = x[b,f,idx[b,k]]. 2048 blocks -> full chip.
// Coalesced 64B writes per (b,f) row; scattered 4B reads are L2/DRAM-friendly.
// ---------------------------------------------------------------------------
__global__ void gather_kernel(const float* __restrict__ x,
                              float* __restrict__ out) {
    const int i = blockIdx.x * blockDim.x + threadIdx.x;
    if (i >= B * F * KK) return;
    const int k = i & (KK - 1);
    const int f = (i >> 4) & (F - 1);
    const int b = i >> 14;
    const int col = g_idx[b * KK + k];
    out[i] = __ldg(x + (size_t)b * F * S + (size_t)f * S + col);
}

// ---------------------------------------------------------------------------
extern "C" void kernel_launch(void* const* d_in, const int* in_sizes, int n_in,
                              void* d_out, int out_size) {
    const float* x = (const float*)d_in[0];  // [B, F, S]
    const float* w = (const float*)d_in[1];  // [B, S, S]
    float* out = (float*)d_out;              // [B, F, K]

    dim3 g1(S / (128 * 4), NSPLIT, B);       // (4, 8, 32) = 1024 blocks
    colsum_topk_kernel<<<g1, 128>>>(w);

    const int total = B * F * KK;            // 524288
    gather_kernel<<<total / 256, 256>>>(x, out);
}

// round 13
// speedup vs baseline: 1.0021x; 1.0021x over previous
#include <cuda_runtime.h>
#include <cstdint>

#define B 32
#define F 1024
#define S 2048
#define KK 16
#define NSPLIT 8
#define RPS (S / NSPLIT)          // 256 rows per split
#define BLKS_PER_BATCH 32         // (S/(128*4)) * NSPLIT = 4*8

// Scratch (allocation-free rule: __device__ globals)
__device__ float g_partial[B * NSPLIT * S];   // 2 MB partial column sums
__device__ int   g_idx[B * KK];               // top-k indices per batch
__device__ unsigned int g_count[B];           // arrival counters (self-reset)

static __device__ __forceinline__ unsigned long long u64max(
    unsigned long long a, unsigned long long b) { return a > b ? a : b; }

// ---------------------------------------------------------------------------
// Kernel 1 (fused): partial column sums of w[B,S,S] + last-block-per-batch
// fold & top-16 epilogue.
// Main body = EXACT measured-best colsum (float4 __ldg, unroll 8, 128 thr).
// Epilogue (32nd arriving block of the batch only):
//   - fold 8 partials (L2-hot), build packed sort keys in smem,
//   - quad-shuffle group maxes (32 groups of 64 cols),
//   - warp-0 tournament: 16 rounds of {5-shfl argmax, mask winner,
//     64-entry group rescan, 5-shfl reduce} — no block barriers per round.
// Key = (monotone float bits << 32) | (S-1-col): max key = largest value,
// ties broken toward the LOWEST column index (matches lax.top_k).
// ---------------------------------------------------------------------------
__global__ void colsum_topk_kernel(const float* __restrict__ w) {
    __shared__ unsigned long long skey[S];          // 16 KB
    __shared__ unsigned long long groupmax[32];
    __shared__ int s_last;

    const int c4    = blockIdx.x * blockDim.x + threadIdx.x;  // float4 col group
    const int split = blockIdx.y;
    const int b     = blockIdx.z;
    const int t     = threadIdx.x;                  // 0..127
    const int lane  = t & 31;

    // ---- colsum main body (DO NOT TOUCH: 83.7% DRAM measured) ----
    const float4* wp = reinterpret_cast<const float4*>(w + (size_t)b * S * S);
    const float4* p  = wp + (size_t)(split * RPS) * (S / 4) + c4;

    float4 acc = make_float4(0.f, 0.f, 0.f, 0.f);
#pragma unroll 8
    for (int r = 0; r < RPS; ++r) {
        float4 v = __ldg(p);
        acc.x += v.x; acc.y += v.y; acc.z += v.z; acc.w += v.w;
        p += S / 4;
    }

    float4* outp = reinterpret_cast<float4*>(g_partial)
                 + (size_t)(b * NSPLIT + split) * (S / 4) + c4;
    *outp = acc;

    // ---- arrival count (threadfence-reduction pattern) ----
    __threadfence();
    __syncthreads();
    if (t == 0) {
        unsigned int old = atomicInc(&g_count[b], BLKS_PER_BATCH - 1);
        s_last = (old == BLKS_PER_BATCH - 1);       // wraps to 0: replay-safe
    }
    __syncthreads();
    if (!s_last) return;

    // ---- epilogue: fold 8 partials for this batch (thread t: cols 16t..16t+15)
    unsigned long long kmax = 0ull;
#pragma unroll
    for (int j = 0; j < 4; ++j) {
        const int g4 = 4 * t + j;                   // float4 col group
        float4 s = make_float4(0.f, 0.f, 0.f, 0.f);
#pragma unroll
        for (int pp = 0; pp < NSPLIT; ++pp) {
            float4 v = *(reinterpret_cast<const float4*>(g_partial)
                         + (size_t)(b * NSPLIT + pp) * (S / 4) + g4);
            s.x += v.x; s.y += v.y; s.z += v.z; s.w += v.w;
        }
        const float sv[4] = {s.x, s.y, s.z, s.w};
#pragma unroll
        for (int e = 0; e < 4; ++e) {
            const int c = 4 * g4 + e;
            unsigned int bits = __float_as_uint(sv[e]);
            bits = (bits & 0x80000000u) ? ~bits : (bits | 0x80000000u);
            unsigned long long key = ((unsigned long long)bits << 32)
                                   | (unsigned int)(S - 1 - c);
            skey[c] = key;
            kmax = u64max(kmax, key);
        }
    }
    // quad reduce: threads 4q..4q+3 cover 64-col group q
    kmax = u64max(kmax, __shfl_down_sync(0xffffffffu, kmax, 2, 4));
    kmax = u64max(kmax, __shfl_down_sync(0xffffffffu, kmax, 1, 4));
    if ((t & 3) == 0) groupmax[t >> 2] = kmax;
    __syncthreads();

    // ---- warp-0 tournament ----
    if (t < 32) {
        unsigned long long gm = groupmax[lane];     // lane l owns group l

        for (int k = 0; k < KK; ++k) {
            unsigned long long m = gm;
#pragma unroll
            for (int off = 16; off > 0; off >>= 1)
                m = u64max(m, __shfl_down_sync(0xffffffffu, m, off));
            m = __shfl_sync(0xffffffffu, m, 0);

            const int col = S - 1 - (int)(m & 0xFFFFFFFFu);
            if (lane == 0) {
                g_idx[b * KK + k] = col;
                skey[col] = 0ull;                   // mask the winner
            }
            __syncwarp();

            const int g = col >> 6;                 // rescan winner's group
            unsigned long long a0 = skey[(g << 6) + lane];
            unsigned long long a1 = skey[(g << 6) + 32 + lane];
            unsigned long long mm = u64max(a0, a1);
#pragma unroll
            for (int off = 16; off > 0; off >>= 1)
                mm = u64max(mm, __shfl_down_sync(0xffffffffu, mm, off));
            mm = __shfl_sync(0xffffffffu, mm, 0);
            if (lane == g) gm = mm;
        }
    }
}

// ---------------------------------------------------------------------------
// Kernel 2: gather out[b,f,k] = x[b,f,idx[b,k]]. 2048 blocks -> full chip.
// Coalesced 64B writes per (b,f) row; scattered 4B reads are L2/DRAM-friendly.
// ---------------------------------------------------------------------------
__global__ void gather_kernel(const float* __restrict__ x,
                              float* __restrict__ out) {
    const int i = blockIdx.x * blockDim.x + threadIdx.x;
    if (i >= B * F * KK) return;
    const int k = i & (KK - 1);
    const int f = (i >> 4) & (F - 1);
    const int b = i >> 14;
    const int col = g_idx[b * KK + k];
    out[i] = __ldg(x + (size_t)b * F * S + (size_t)f * S + col);
}

// ---------------------------------------------------------------------------
extern "C" void kernel_launch(void* const* d_in, const int* in_sizes, int n_in,
                              void* d_out, int out_size) {
    const float* x = (const float*)d_in[0];  // [B, F, S]
    const float* w = (const float*)d_in[1];  // [B, S, S]
    float* out = (float*)d_out;              // [B, F, K]

    dim3 g1(S / (128 * 4), NSPLIT, B);       // (4, 8, 32) = 1024 blocks
    colsum_topk_kernel<<<g1, 128>>>(w);

    const int total = B * F * KK;            // 524288
    gather_kernel<<<total / 256, 256>>>(x, out);
}